// round 2
// baseline (speedup 1.0000x reference)
#include <cuda_runtime.h>
#include <math.h>

// ---- problem constants ----
#define BW      1024
#define LW      144          // window area
#define CDIM    256
#define HEADS   8
#define DH      32
#define KDIM    256
#define NQKV    768
#define MH      384          // meta hidden
#define LOGIT_MAX 4.605170185988091f   // log(100)

// ---- scratch (static device memory; no allocation allowed) ----
__device__ float g_q[BW*HEADS*LW*DH];
__device__ float g_k[BW*HEADS*LW*DH];
__device__ float g_v[BW*HEADS*LW*DH];
__device__ float g_ao[BW*LW*CDIM];
__device__ float g_bias[HEADS*LW*LW];

// ============================================================
// f32x2 packed helpers (sm_103a full-rate fp32 path)
// ============================================================
__device__ __forceinline__ unsigned long long pack2(float x, float y) {
    unsigned long long r;
    asm("mov.b64 %0, {%1, %2};" : "=l"(r) : "r"(__float_as_uint(x)), "r"(__float_as_uint(y)));
    return r;
}
__device__ __forceinline__ float2 unpack2(unsigned long long v) {
    unsigned int lo, hi;
    asm("mov.b64 {%0, %1}, %2;" : "=r"(lo), "=r"(hi) : "l"(v));
    return make_float2(__uint_as_float(lo), __uint_as_float(hi));
}
__device__ __forceinline__ unsigned long long fma2(unsigned long long a,
                                                   unsigned long long b,
                                                   unsigned long long c) {
    unsigned long long d;
    asm("fma.rn.f32x2 %0, %1, %2, %3;" : "=l"(d) : "l"(a), "l"(b), "l"(c));
    return d;
}

// FMA-only expf substitute (MUFU rt=8 makes __expf a bottleneck at 170M calls).
// x <= 0 expected. 2^(x*log2e) via rint split + degree-5 poly. rel err ~2.4e-6.
__device__ __forceinline__ float fast_exp(float x) {
    x = fmaxf(x, -87.0f);
    float y = x * 1.4426950408889634f;
    float n = rintf(y);
    float f = y - n;
    float p = 1.3333558146e-3f;
    p = fmaf(p, f, 9.6181291076e-3f);
    p = fmaf(p, f, 5.5504108664e-2f);
    p = fmaf(p, f, 2.4022650696e-1f);
    p = fmaf(p, f, 6.9314718056e-1f);
    p = fmaf(p, f, 1.0f);
    return p * __int_as_float(((int)n + 127) << 23);
}

// ============================================================
// 1) Meta-MLP relative position bias table: g_bias[h][i][j]
// ============================================================
__global__ void bias_kernel(const float* __restrict__ fc1_w, const float* __restrict__ fc1_b,
                            const float* __restrict__ fc2_w, const float* __restrict__ fc2_b) {
    int idx = blockIdx.x * blockDim.x + threadIdx.x;  // 0 .. 144*144-1
    if (idx >= LW*LW) return;
    int i = idx / LW, j = idx % LW;
    float dy = (float)(i / 12 - j / 12);
    float dx = (float)(i % 12 - j % 12);
    // sign(d)*log1p(|d|) (copysign handles 0 correctly)
    float ry = copysignf(log1pf(fabsf(dy)), dy);
    float rx = copysignf(log1pf(fabsf(dx)), dx);

    float out[HEADS];
    #pragma unroll
    for (int hh = 0; hh < HEADS; hh++) out[hh] = 0.0f;

    for (int t = 0; t < MH; t++) {
        float hsum = fmaf(fc1_w[t*2], ry, fmaf(fc1_w[t*2+1], rx, fc1_b[t]));
        hsum = fmaxf(hsum, 0.0f);
        #pragma unroll
        for (int hh = 0; hh < HEADS; hh++)
            out[hh] = fmaf(fc2_w[hh*MH + t], hsum, out[hh]);
    }
    #pragma unroll
    for (int hh = 0; hh < HEADS; hh++)
        g_bias[hh*LW*LW + idx] = out[hh] + fc2_b[hh];
}

// ============================================================
// SIMT fp32x2 GEMM mainloop: C[128x128] += A(MxK) * B(NxK)^T
// 256 threads, 8x8 microtile per thread, K-tile 16.
// As/Bs staged transposed [16][128] with +4 pad (float4-aligned).
// ============================================================
#define SPITCH 132

__device__ __forceinline__ void gemm_mainloop(const float* __restrict__ A,
                                              const float* __restrict__ B,
                                              int K, int m0, int n0,
                                              float* As, float* Bs,
                                              int tid, int tx, int ty,
                                              unsigned long long acc[4][8]) {
    #pragma unroll
    for (int i2 = 0; i2 < 4; i2++)
        #pragma unroll
        for (int j = 0; j < 8; j++) acc[i2][j] = 0ULL;  // (0.f, 0.f)

    int lr = tid >> 2;           // 0..63
    int lc = (tid & 3) << 2;     // 0,4,8,12

    for (int k0 = 0; k0 < K; k0 += 16) {
        #pragma unroll
        for (int rr = 0; rr < 2; rr++) {
            int r = lr + rr * 64;
            float4 av = *(const float4*)(A + (long)(m0 + r) * K + k0 + lc);
            As[(lc+0)*SPITCH + r] = av.x;
            As[(lc+1)*SPITCH + r] = av.y;
            As[(lc+2)*SPITCH + r] = av.z;
            As[(lc+3)*SPITCH + r] = av.w;
            float4 bv = *(const float4*)(B + (long)(n0 + r) * K + k0 + lc);
            Bs[(lc+0)*SPITCH + r] = bv.x;
            Bs[(lc+1)*SPITCH + r] = bv.y;
            Bs[(lc+2)*SPITCH + r] = bv.z;
            Bs[(lc+3)*SPITCH + r] = bv.w;
        }
        __syncthreads();
        #pragma unroll
        for (int kk = 0; kk < 16; kk++) {
            const ulonglong2* ar = (const ulonglong2*)(As + kk*SPITCH + ty*8);
            ulonglong2 a01 = ar[0];
            ulonglong2 a23 = ar[1];
            unsigned long long ap[4] = {a01.x, a01.y, a23.x, a23.y};
            float4 b0 = *(const float4*)(Bs + kk*SPITCH + tx*8);
            float4 b1 = *(const float4*)(Bs + kk*SPITCH + tx*8 + 4);
            unsigned long long bp[8];
            bp[0] = pack2(b0.x, b0.x); bp[1] = pack2(b0.y, b0.y);
            bp[2] = pack2(b0.z, b0.z); bp[3] = pack2(b0.w, b0.w);
            bp[4] = pack2(b1.x, b1.x); bp[5] = pack2(b1.y, b1.y);
            bp[6] = pack2(b1.z, b1.z); bp[7] = pack2(b1.w, b1.w);
            #pragma unroll
            for (int i2 = 0; i2 < 4; i2++)
                #pragma unroll
                for (int j = 0; j < 8; j++)
                    acc[i2][j] = fma2(ap[i2], bp[j], acc[i2][j]);
        }
        __syncthreads();
    }
}

// ============================================================
// 2) QKV GEMM: X(M=Bw*144, K=256) * qkv_w(768,256)^T + qkv_b
//    Scattered epilogue into q/k/v [(b*8+h)*144 + l][d]
// ============================================================
__global__ __launch_bounds__(256) void qkv_gemm_kernel(const float* __restrict__ X,
                                                       const float* __restrict__ W,
                                                       const float* __restrict__ bias) {
    __shared__ __align__(16) float As[16*SPITCH];
    __shared__ __align__(16) float Bs[16*SPITCH];
    int tid = threadIdx.x;
    int tx = tid & 15, ty = tid >> 4;
    int m0 = blockIdx.y * 128;
    int n0b = blockIdx.x * 128;

    unsigned long long acc[4][8];
    gemm_mainloop(X, W, KDIM, m0, n0b, As, Bs, tid, tx, ty, acc);

    int n0 = n0b + tx * 8;
    int part = n0 >> 8;           // 0=q 1=k 2=v
    int h = (n0 >> 5) & 7;
    int d0 = n0 & 31;             // 8-aligned, stays within one head
    float* dst = (part == 0) ? g_q : ((part == 1) ? g_k : g_v);

    float bb[8];
    #pragma unroll
    for (int j = 0; j < 8; j++) bb[j] = bias[n0 + j];

    #pragma unroll
    for (int i2 = 0; i2 < 4; i2++) {
        float2 f[8];
        #pragma unroll
        for (int j = 0; j < 8; j++) f[j] = unpack2(acc[i2][j]);
        #pragma unroll
        for (int s = 0; s < 2; s++) {
            int m = m0 + ty * 8 + i2 * 2 + s;
            int b = m / LW, l = m % LW;
            float* o = dst + ((long)(b * HEADS + h) * LW + l) * DH + d0;
            float v0 = (s ? f[0].y : f[0].x) + bb[0];
            float v1 = (s ? f[1].y : f[1].x) + bb[1];
            float v2 = (s ? f[2].y : f[2].x) + bb[2];
            float v3 = (s ? f[3].y : f[3].x) + bb[3];
            float v4 = (s ? f[4].y : f[4].x) + bb[4];
            float v5 = (s ? f[5].y : f[5].x) + bb[5];
            float v6 = (s ? f[6].y : f[6].x) + bb[6];
            float v7 = (s ? f[7].y : f[7].x) + bb[7];
            *(float4*)(o + 0) = make_float4(v0, v1, v2, v3);
            *(float4*)(o + 4) = make_float4(v4, v5, v6, v7);
        }
    }
}

// ============================================================
// 3) Windowed cosine attention, one block per (head, window)
//    160 threads (5 warps), thread t<144 owns query row t.
// ============================================================
#define KPITCH 36   // 32 + 4 pad, keeps float4 alignment (144B rows)

__global__ __launch_bounds__(160) void attn_kernel(const float* __restrict__ mask,
                                                   const float* __restrict__ logit_scale,
                                                   int num_win) {
    __shared__ __align__(16) float kn[LW * KPITCH];
    __shared__ __align__(16) float vv[LW * KPITCH];

    int h = blockIdx.x;
    int b = blockIdx.y;
    int t = threadIdx.x;
    long bh = (long)(b * HEADS + h) * LW;

    if (t < LW) {
        // normalize K row into smem; copy V row
        const float4* kp = (const float4*)(g_k + (bh + t) * DH);
        float4 r[8];
        float ss = 0.0f;
        #pragma unroll
        for (int i = 0; i < 8; i++) {
            r[i] = kp[i];
            ss = fmaf(r[i].x, r[i].x, ss); ss = fmaf(r[i].y, r[i].y, ss);
            ss = fmaf(r[i].z, r[i].z, ss); ss = fmaf(r[i].w, r[i].w, ss);
        }
        float inv = 1.0f / fmaxf(sqrtf(ss), 1e-12f);
        #pragma unroll
        for (int i = 0; i < 8; i++) {
            *(float4*)(kn + t * KPITCH + i * 4) =
                make_float4(r[i].x * inv, r[i].y * inv, r[i].z * inv, r[i].w * inv);
        }
        const float4* vp = (const float4*)(g_v + (bh + t) * DH);
        #pragma unroll
        for (int i = 0; i < 8; i++)
            *(float4*)(vv + t * KPITCH + i * 4) = vp[i];
    }
    __syncthreads();
    if (t >= LW) return;

    // Q row: normalize and fold in logit scale
    float scale = expf(fminf(logit_scale[h], LOGIT_MAX));
    const float4* qp = (const float4*)(g_q + (bh + t) * DH);
    float4 q[8];
    float ss = 0.0f;
    #pragma unroll
    for (int i = 0; i < 8; i++) {
        q[i] = qp[i];
        ss = fmaf(q[i].x, q[i].x, ss); ss = fmaf(q[i].y, q[i].y, ss);
        ss = fmaf(q[i].z, q[i].z, ss); ss = fmaf(q[i].w, q[i].w, ss);
    }
    float inv = scale / fmaxf(sqrtf(ss), 1e-12f);
    unsigned long long q2[16];
    #pragma unroll
    for (int i = 0; i < 8; i++) {
        q2[2*i+0] = pack2(q[i].x * inv, q[i].y * inv);
        q2[2*i+1] = pack2(q[i].z * inv, q[i].w * inv);
    }

    const float* brow = g_bias + (h * LW + t) * LW;
    const float* mrow = mask + ((long)(b % num_win) * LW + t) * LW;

    float logits[LW];
    float M = -1e30f;

    // pass 1: logits + max (dot via packed f32x2)
    #pragma unroll 1
    for (int m4 = 0; m4 < LW; m4 += 4) {
        float4 bv = *(const float4*)(brow + m4);
        float4 mv = *(const float4*)(mrow + m4);
        float ba[4] = {bv.x + mv.x, bv.y + mv.y, bv.z + mv.z, bv.w + mv.w};
        #pragma unroll
        for (int u = 0; u < 4; u++) {
            int m = m4 + u;
            const ulonglong2* krow = (const ulonglong2*)(kn + m * KPITCH);
            unsigned long long dacc = 0ULL;
            #pragma unroll
            for (int i = 0; i < 8; i++) {
                ulonglong2 kk = krow[i];
                dacc = fma2(q2[2*i+0], kk.x, dacc);
                dacc = fma2(q2[2*i+1], kk.y, dacc);
            }
            float2 dd = unpack2(dacc);
            float logit = dd.x + dd.y + ba[u];
            logits[m] = logit;
            M = fmaxf(M, logit);
        }
    }

    // pass 2: exp + weighted V accumulation
    float S = 0.0f;
    unsigned long long acc[16];
    #pragma unroll
    for (int i = 0; i < 16; i++) acc[i] = 0ULL;

    #pragma unroll 1
    for (int m = 0; m < LW; m++) {
        float p = fast_exp(logits[m] - M);
        S += p;
        unsigned long long pp = pack2(p, p);
        const ulonglong2* vrow = (const ulonglong2*)(vv + m * KPITCH);
        #pragma unroll
        for (int i = 0; i < 8; i++) {
            ulonglong2 vk = vrow[i];
            acc[2*i+0] = fma2(pp, vk.x, acc[2*i+0]);
            acc[2*i+1] = fma2(pp, vk.y, acc[2*i+1]);
        }
    }

    float rS = 1.0f / S;
    float* op = g_ao + ((long)b * LW + t) * CDIM + h * DH;
    #pragma unroll
    for (int i = 0; i < 8; i++) {
        float2 f0 = unpack2(acc[2*i+0]);
        float2 f1 = unpack2(acc[2*i+1]);
        *(float4*)(op + i * 4) =
            make_float4(f0.x * rS, f0.y * rS, f1.x * rS, f1.y * rS);
    }
}

// ============================================================
// 4) Output projection: g_ao(M,256) * proj_w(256,256)^T + proj_b
// ============================================================
__global__ __launch_bounds__(256) void proj_gemm_kernel(const float* __restrict__ W,
                                                        const float* __restrict__ bias,
                                                        float* __restrict__ out) {
    __shared__ __align__(16) float As[16*SPITCH];
    __shared__ __align__(16) float Bs[16*SPITCH];
    int tid = threadIdx.x;
    int tx = tid & 15, ty = tid >> 4;
    int m0 = blockIdx.y * 128;
    int n0b = blockIdx.x * 128;

    unsigned long long acc[4][8];
    gemm_mainloop(g_ao, W, CDIM, m0, n0b, As, Bs, tid, tx, ty, acc);

    int n0 = n0b + tx * 8;
    float bb[8];
    #pragma unroll
    for (int j = 0; j < 8; j++) bb[j] = bias[n0 + j];

    #pragma unroll
    for (int i2 = 0; i2 < 4; i2++) {
        float2 f[8];
        #pragma unroll
        for (int j = 0; j < 8; j++) f[j] = unpack2(acc[i2][j]);
        #pragma unroll
        for (int s = 0; s < 2; s++) {
            int m = m0 + ty * 8 + i2 * 2 + s;
            float* o = out + (long)m * CDIM + n0;
            float v0 = (s ? f[0].y : f[0].x) + bb[0];
            float v1 = (s ? f[1].y : f[1].x) + bb[1];
            float v2 = (s ? f[2].y : f[2].x) + bb[2];
            float v3 = (s ? f[3].y : f[3].x) + bb[3];
            float v4 = (s ? f[4].y : f[4].x) + bb[4];
            float v5 = (s ? f[5].y : f[5].x) + bb[5];
            float v6 = (s ? f[6].y : f[6].x) + bb[6];
            float v7 = (s ? f[7].y : f[7].x) + bb[7];
            *(float4*)(o + 0) = make_float4(v0, v1, v2, v3);
            *(float4*)(o + 4) = make_float4(v4, v5, v6, v7);
        }
    }
}

// ============================================================
// launch
// ============================================================
extern "C" void kernel_launch(void* const* d_in, const int* in_sizes, int n_in,
                              void* d_out, int out_size) {
    const float* x           = (const float*)d_in[0];
    const float* mask        = (const float*)d_in[1];
    const float* qkv_w       = (const float*)d_in[2];
    const float* qkv_b       = (const float*)d_in[3];
    const float* proj_w      = (const float*)d_in[4];
    const float* proj_b      = (const float*)d_in[5];
    const float* fc1_w       = (const float*)d_in[6];
    const float* fc1_b       = (const float*)d_in[7];
    const float* fc2_w       = (const float*)d_in[8];
    const float* fc2_b       = (const float*)d_in[9];
    const float* logit_scale = (const float*)d_in[10];

    int Bw = in_sizes[0] / (LW * CDIM);          // 1024
    int num_win = in_sizes[1] / (LW * LW);       // 64
    int Mrows = Bw * LW;                         // 147456 (divisible by 128)

    bias_kernel<<<(LW*LW + 63) / 64, 64>>>(fc1_w, fc1_b, fc2_w, fc2_b);
    qkv_gemm_kernel<<<dim3(NQKV / 128, Mrows / 128), 256>>>(x, qkv_w, qkv_b);
    attn_kernel<<<dim3(HEADS, Bw), 160>>>(mask, logit_scale, num_win);
    proj_gemm_kernel<<<dim3(CDIM / 128, Mrows / 128), 256>>>(proj_w, proj_b, (float*)d_out);
}

// round 5
// speedup vs baseline: 1.7178x; 1.7178x over previous
#include <cuda_runtime.h>
#include <math.h>

typedef unsigned int       u32;
typedef unsigned long long u64;

// ---- problem constants ----
#define BW      1024
#define LW      144
#define CDIM    256
#define HEADS   8
#define DH      32
#define KDIM    256
#define NQKV    768
#define MH      384
#define LOGIT_MAX 4.605170185988091f

// ---- scratch ----
__device__ float g_q[BW*HEADS*LW*DH];
__device__ float g_k[BW*HEADS*LW*DH];
__device__ float g_v[BW*HEADS*LW*DH];
__device__ float g_ao[BW*LW*CDIM];
__device__ float g_bias[HEADS*LW*LW];

// ============================================================
// helpers
// ============================================================
__device__ __forceinline__ u64 pack2(float x, float y) {
    u64 r;
    asm("mov.b64 %0, {%1, %2};" : "=l"(r) : "r"(__float_as_uint(x)), "r"(__float_as_uint(y)));
    return r;
}
__device__ __forceinline__ float2 unpack2(u64 v) {
    u32 lo, hi;
    asm("mov.b64 {%0, %1}, %2;" : "=r"(lo), "=r"(hi) : "l"(v));
    return make_float2(__uint_as_float(lo), __uint_as_float(hi));
}
__device__ __forceinline__ u64 fma2(u64 a, u64 b, u64 c) {
    u64 d;
    asm("fma.rn.f32x2 %0, %1, %2, %3;" : "=l"(d) : "l"(a), "l"(b), "l"(c));
    return d;
}
__device__ __forceinline__ float fast_exp(float x) {
    x = fmaxf(x, -87.0f);
    float y = x * 1.4426950408889634f;
    float n = rintf(y);
    float f = y - n;
    float p = 1.3333558146e-3f;
    p = fmaf(p, f, 9.6181291076e-3f);
    p = fmaf(p, f, 5.5504108664e-2f);
    p = fmaf(p, f, 2.4022650696e-1f);
    p = fmaf(p, f, 6.9314718056e-1f);
    p = fmaf(p, f, 1.0f);
    return p * __int_as_float(((int)n + 127) << 23);
}
__device__ __forceinline__ u32 smem_u32(const void* p) {
    u32 a;
    asm("{ .reg .u64 t; cvta.to.shared.u64 t, %1; cvt.u32.u64 %0, t; }" : "=r"(a) : "l"(p));
    return a;
}
// pack two f32 -> bf16x2 (round-to-nearest). d<31:16>=hi, d<15:0>=lo
__device__ __forceinline__ u32 bf16x2_rn(float lo, float hi) {
    u32 r; asm("cvt.rn.bf16x2.f32 %0, %1, %2;" : "=r"(r) : "f"(hi), "f"(lo)); return r;
}
__device__ __forceinline__ void ldsm4(u32* r, u32 addr) {
    asm volatile("ldmatrix.sync.aligned.m8n8.x4.shared.b16 {%0,%1,%2,%3}, [%4];"
        : "=r"(r[0]), "=r"(r[1]), "=r"(r[2]), "=r"(r[3]) : "r"(addr));
}
__device__ __forceinline__ void mma_bf16(float* d, const u32* a, u32 b0, u32 b1) {
    asm volatile("mma.sync.aligned.m16n8k16.row.col.f32.bf16.bf16.f32 "
        "{%0,%1,%2,%3}, {%4,%5,%6,%7}, {%8,%9}, {%0,%1,%2,%3};"
        : "+f"(d[0]), "+f"(d[1]), "+f"(d[2]), "+f"(d[3])
        : "r"(a[0]), "r"(a[1]), "r"(a[2]), "r"(a[3]), "r"(b0), "r"(b1));
}

// ============================================================
// 1) bias table (meta MLP)
// ============================================================
__global__ void bias_kernel(const float* __restrict__ fc1_w, const float* __restrict__ fc1_b,
                            const float* __restrict__ fc2_w, const float* __restrict__ fc2_b) {
    int idx = blockIdx.x * blockDim.x + threadIdx.x;
    if (idx >= LW*LW) return;
    int i = idx / LW, j = idx % LW;
    float dy = (float)(i / 12 - j / 12);
    float dx = (float)(i % 12 - j % 12);
    float ry = copysignf(log1pf(fabsf(dy)), dy);
    float rx = copysignf(log1pf(fabsf(dx)), dx);

    float out[HEADS];
    #pragma unroll
    for (int hh = 0; hh < HEADS; hh++) out[hh] = 0.0f;
    for (int t = 0; t < MH; t++) {
        float hsum = fmaf(fc1_w[t*2], ry, fmaf(fc1_w[t*2+1], rx, fc1_b[t]));
        hsum = fmaxf(hsum, 0.0f);
        #pragma unroll
        for (int hh = 0; hh < HEADS; hh++)
            out[hh] = fmaf(fc2_w[hh*MH + t], hsum, out[hh]);
    }
    #pragma unroll
    for (int hh = 0; hh < HEADS; hh++)
        g_bias[hh*LW*LW + idx] = out[hh] + fc2_b[hh];
}

// ============================================================
// mma.sync bf16x3 GEMM: C[128,128] = A(m0..,K=256) * B(n0..,K=256)^T
// 8 warps (4x2), warp tile 32x64, K-tile 32 (2 k16 steps).
// A staged natural bf16 rows (80B pitch, conflict-free ldmatrix).
// B staged in fragment order: [s][nt][lane]{b0h,b1h,b0l,b1l} -> LDS.128.
// ============================================================
#define APITCH 80

__device__ __forceinline__ void stage_tile(const float* __restrict__ A,
                                           const float* __restrict__ B,
                                           int m0, int n0, int kt,
                                           char* sAhi, char* sAlo, char* sBf) {
    int tid = threadIdx.x;
    #pragma unroll
    for (int j = 0; j < 8; j++) {
        int i = tid + j * 256;
        int ii = i & 1023;
        int row = ii >> 3, c4 = ii & 7;
        const float* src = (i < 1024)
            ? (A + (long)(m0 + row) * KDIM + kt * 32 + c4 * 4)
            : (B + (long)(n0 + row) * KDIM + kt * 32 + c4 * 4);
        float4 v = *(const float4*)src;
        u32 h01 = bf16x2_rn(v.x, v.y);
        u32 h23 = bf16x2_rn(v.z, v.w);
        float hx = __uint_as_float(h01 << 16);
        float hy = __uint_as_float(h01 & 0xFFFF0000u);
        float hz = __uint_as_float(h23 << 16);
        float hw = __uint_as_float(h23 & 0xFFFF0000u);
        u32 l01 = bf16x2_rn(v.x - hx, v.y - hy);
        u32 l23 = bf16x2_rn(v.z - hz, v.w - hw);
        if (i < 1024) {
            int off = row * APITCH + c4 * 8;
            *(uint2*)(sAhi + off) = make_uint2(h01, h23);
            *(uint2*)(sAlo + off) = make_uint2(l01, l23);
        } else {
            int s = c4 >> 2;                 // k16 step
            int khalf = (c4 >> 1) & 1;       // b0 vs b1
            int l = ((row & 7) << 2) + ((c4 & 1) << 1);
            int nt = row >> 3;
            int base = ((s * 16 + nt) * 32 + l) << 4;
            *(u32*)(sBf + base + khalf * 4)       = h01;   // pair (k0,k0+1) hi
            *(u32*)(sBf + base + 8 + khalf * 4)   = l01;   // lo
            *(u32*)(sBf + base + 16 + khalf * 4)  = h23;   // pair (k0+2,k0+3) -> lane l+1
            *(u32*)(sBf + base + 24 + khalf * 4)  = l23;
        }
    }
}

struct GemmSmem {
    __align__(16) char sAhi[128 * APITCH];
    __align__(16) char sAlo[128 * APITCH];
    __align__(16) char sBf[2 * 16 * 32 * 16];
};

__device__ __forceinline__ void gemm_mma(const float* __restrict__ A,
                                         const float* __restrict__ B,
                                         int m0, int n0,
                                         GemmSmem* sm, float acc[2][8][4]) {
    int tid = threadIdx.x, lane = tid & 31, wid = tid >> 5;
    int wm = wid >> 1, wn = wid & 1;

    #pragma unroll
    for (int mt = 0; mt < 2; mt++)
        #pragma unroll
        for (int nt = 0; nt < 8; nt++)
            #pragma unroll
            for (int c = 0; c < 4; c++) acc[mt][nt][c] = 0.0f;

    u32 aAhi = smem_u32(sm->sAhi), aAlo = smem_u32(sm->sAlo);
    u32 rowA = (u32)((wm * 32 + (lane & 15)) * APITCH + ((lane >> 4) << 4));

    for (int kt = 0; kt < 8; kt++) {
        stage_tile(A, B, m0, n0, kt, sm->sAhi, sm->sAlo, sm->sBf);
        __syncthreads();
        #pragma unroll
        for (int s = 0; s < 2; s++) {
            u32 ah[2][4], al[2][4];
            #pragma unroll
            for (int mt = 0; mt < 2; mt++) {
                u32 ad = rowA + mt * 16 * APITCH + s * 32;
                ldsm4(ah[mt], aAhi + ad);
                ldsm4(al[mt], aAlo + ad);
            }
            #pragma unroll
            for (int nt2 = 0; nt2 < 8; nt2++) {
                uint4 b = *(const uint4*)(sm->sBf +
                    (((s * 16 + wn * 8 + nt2) * 32 + lane) << 4));
                #pragma unroll
                for (int mt = 0; mt < 2; mt++) {
                    mma_bf16(acc[mt][nt2], ah[mt], b.x, b.y);  // hi*hi
                    mma_bf16(acc[mt][nt2], al[mt], b.x, b.y);  // lo*hi
                    mma_bf16(acc[mt][nt2], ah[mt], b.z, b.w);  // hi*lo
                }
            }
        }
        __syncthreads();
    }
}

// ============================================================
// 2) QKV GEMM kernel: X * qkv_w^T + qkv_b -> scattered g_q/g_k/g_v
// ============================================================
__global__ void __launch_bounds__(256, 2)
qkv_mma_kernel(const float* __restrict__ X, const float* __restrict__ W,
               const float* __restrict__ bias) {
    __shared__ GemmSmem sm;
    int m0 = blockIdx.y * 128;
    int n0 = blockIdx.x * 128;
    float acc[2][8][4];
    gemm_mma(X, W, m0, n0, &sm, acc);

    int lane = threadIdx.x & 31, wid = threadIdx.x >> 5;
    int wm = wid >> 1, wn = wid & 1;
    int r = lane >> 2, cp = (lane & 3) * 2;

    #pragma unroll
    for (int mt = 0; mt < 2; mt++) {
        #pragma unroll
        for (int half = 0; half < 2; half++) {
            int m = m0 + wm * 32 + mt * 16 + r + half * 8;
            int b = m / LW, l = m % LW;
            #pragma unroll
            for (int nt2 = 0; nt2 < 8; nt2++) {
                int col = n0 + wn * 64 + nt2 * 8 + cp;
                int part = col >> 8;
                int h = (col >> 5) & 7;
                int d0 = col & 31;
                float* dst = (part == 0) ? g_q : ((part == 1) ? g_k : g_v);
                float2 v;
                v.x = acc[mt][nt2][half * 2 + 0] + bias[col];
                v.y = acc[mt][nt2][half * 2 + 1] + bias[col + 1];
                *(float2*)(dst + ((long)(b * HEADS + h) * LW + l) * DH + d0) = v;
            }
        }
    }
}

// ============================================================
// 3) Attention: online softmax (no logits array, no spill)
// ============================================================
#define KPITCH 36

__global__ __launch_bounds__(160) void attn_kernel(const float* __restrict__ mask,
                                                   const float* __restrict__ logit_scale,
                                                   int num_win) {
    __shared__ __align__(16) float kn[LW * KPITCH];
    __shared__ __align__(16) float vv[LW * KPITCH];

    int h = blockIdx.x;
    int b = blockIdx.y;
    int t = threadIdx.x;
    long bh = (long)(b * HEADS + h) * LW;

    if (t < LW) {
        const float4* kp = (const float4*)(g_k + (bh + t) * DH);
        float4 r[8];
        float ss = 0.0f;
        #pragma unroll
        for (int i = 0; i < 8; i++) {
            r[i] = kp[i];
            ss = fmaf(r[i].x, r[i].x, ss); ss = fmaf(r[i].y, r[i].y, ss);
            ss = fmaf(r[i].z, r[i].z, ss); ss = fmaf(r[i].w, r[i].w, ss);
        }
        float inv = 1.0f / fmaxf(sqrtf(ss), 1e-12f);
        #pragma unroll
        for (int i = 0; i < 8; i++) {
            *(float4*)(kn + t * KPITCH + i * 4) =
                make_float4(r[i].x * inv, r[i].y * inv, r[i].z * inv, r[i].w * inv);
        }
        const float4* vp = (const float4*)(g_v + (bh + t) * DH);
        #pragma unroll
        for (int i = 0; i < 8; i++)
            *(float4*)(vv + t * KPITCH + i * 4) = vp[i];
    }
    __syncthreads();
    if (t >= LW) return;

    float scale = fast_exp(fminf(logit_scale[h], LOGIT_MAX));
    const float4* qp = (const float4*)(g_q + (bh + t) * DH);
    float4 q[8];
    float ss = 0.0f;
    #pragma unroll
    for (int i = 0; i < 8; i++) {
        q[i] = qp[i];
        ss = fmaf(q[i].x, q[i].x, ss); ss = fmaf(q[i].y, q[i].y, ss);
        ss = fmaf(q[i].z, q[i].z, ss); ss = fmaf(q[i].w, q[i].w, ss);
    }
    float inv = scale / fmaxf(sqrtf(ss), 1e-12f);
    u64 q2[16];
    #pragma unroll
    for (int i = 0; i < 8; i++) {
        q2[2*i+0] = pack2(q[i].x * inv, q[i].y * inv);
        q2[2*i+1] = pack2(q[i].z * inv, q[i].w * inv);
    }

    const float* brow = g_bias + (h * LW + t) * LW;
    const float* mrow = mask + ((long)(b % num_win) * LW + t) * LW;

    float M = -1e30f, S = 0.0f;
    u64 acc[16];
    #pragma unroll
    for (int i = 0; i < 16; i++) acc[i] = 0ULL;

    #pragma unroll 1
    for (int m4 = 0; m4 < LW; m4 += 4) {
        float4 bv = *(const float4*)(brow + m4);
        float4 mv = *(const float4*)(mrow + m4);
        float lg[4];
        lg[0] = bv.x + mv.x; lg[1] = bv.y + mv.y;
        lg[2] = bv.z + mv.z; lg[3] = bv.w + mv.w;
        #pragma unroll
        for (int u = 0; u < 4; u++) {
            const ulonglong2* krow = (const ulonglong2*)(kn + (m4 + u) * KPITCH);
            u64 dacc = 0ULL;
            #pragma unroll
            for (int i = 0; i < 8; i++) {
                ulonglong2 kk = krow[i];
                dacc = fma2(q2[2*i+0], kk.x, dacc);
                dacc = fma2(q2[2*i+1], kk.y, dacc);
            }
            float2 dd = unpack2(dacc);
            lg[u] += dd.x + dd.y;
        }
        float gm = fmaxf(fmaxf(lg[0], lg[1]), fmaxf(lg[2], lg[3]));
        if (gm > M) {
            float corr = fast_exp(M - gm);
            M = gm;
            S *= corr;
            u64 c2 = pack2(corr, corr);
            #pragma unroll
            for (int i = 0; i < 16; i++) acc[i] = fma2(acc[i], c2, 0ULL);
        }
        #pragma unroll
        for (int u = 0; u < 4; u++) {
            float p = fast_exp(lg[u] - M);
            S += p;
            u64 pp = pack2(p, p);
            const ulonglong2* vrow = (const ulonglong2*)(vv + (m4 + u) * KPITCH);
            #pragma unroll
            for (int i = 0; i < 8; i++) {
                ulonglong2 vk = vrow[i];
                acc[2*i+0] = fma2(pp, vk.x, acc[2*i+0]);
                acc[2*i+1] = fma2(pp, vk.y, acc[2*i+1]);
            }
        }
    }

    float rS = 1.0f / S;
    float* op = g_ao + ((long)b * LW + t) * CDIM + h * DH;
    #pragma unroll
    for (int i = 0; i < 8; i++) {
        float2 f0 = unpack2(acc[2*i+0]);
        float2 f1 = unpack2(acc[2*i+1]);
        *(float4*)(op + i * 4) =
            make_float4(f0.x * rS, f0.y * rS, f1.x * rS, f1.y * rS);
    }
}

// ============================================================
// 4) Output projection: g_ao * proj_w^T + proj_b
// ============================================================
__global__ void __launch_bounds__(256, 2)
proj_mma_kernel(const float* __restrict__ W, const float* __restrict__ bias,
                float* __restrict__ out) {
    __shared__ GemmSmem sm;
    int m0 = blockIdx.y * 128;
    int n0 = blockIdx.x * 128;
    float acc[2][8][4];
    gemm_mma(g_ao, W, m0, n0, &sm, acc);

    int lane = threadIdx.x & 31, wid = threadIdx.x >> 5;
    int wm = wid >> 1, wn = wid & 1;
    int r = lane >> 2, cp = (lane & 3) * 2;

    #pragma unroll
    for (int mt = 0; mt < 2; mt++) {
        #pragma unroll
        for (int half = 0; half < 2; half++) {
            int m = m0 + wm * 32 + mt * 16 + r + half * 8;
            #pragma unroll
            for (int nt2 = 0; nt2 < 8; nt2++) {
                int col = n0 + wn * 64 + nt2 * 8 + cp;
                float2 v;
                v.x = acc[mt][nt2][half * 2 + 0] + bias[col];
                v.y = acc[mt][nt2][half * 2 + 1] + bias[col + 1];
                *(float2*)(out + (long)m * CDIM + col) = v;
            }
        }
    }
}

// ============================================================
// launch
// ============================================================
extern "C" void kernel_launch(void* const* d_in, const int* in_sizes, int n_in,
                              void* d_out, int out_size) {
    const float* x           = (const float*)d_in[0];
    const float* mask        = (const float*)d_in[1];
    const float* qkv_w       = (const float*)d_in[2];
    const float* qkv_b       = (const float*)d_in[3];
    const float* proj_w      = (const float*)d_in[4];
    const float* proj_b      = (const float*)d_in[5];
    const float* fc1_w       = (const float*)d_in[6];
    const float* fc1_b       = (const float*)d_in[7];
    const float* fc2_w       = (const float*)d_in[8];
    const float* fc2_b       = (const float*)d_in[9];
    const float* logit_scale = (const float*)d_in[10];

    int Bw = in_sizes[0] / (LW * CDIM);       // 1024
    int num_win = in_sizes[1] / (LW * LW);    // 64
    int Mrows = Bw * LW;                      // 147456

    bias_kernel<<<(LW*LW + 63) / 64, 64>>>(fc1_w, fc1_b, fc2_w, fc2_b);
    qkv_mma_kernel<<<dim3(NQKV / 128, Mrows / 128), 256>>>(x, qkv_w, qkv_b);
    attn_kernel<<<dim3(HEADS, Bw), 160>>>(mask, logit_scale, num_win);
    proj_mma_kernel<<<dim3(CDIM / 128, Mrows / 128), 256>>>(proj_w, proj_b, (float*)d_out);
}

// round 7
// speedup vs baseline: 2.3971x; 1.3955x over previous
#include <cuda_runtime.h>
#include <math.h>

typedef unsigned int       u32;
typedef unsigned long long u64;

// ---- problem constants ----
#define BW      1024
#define LW      144
#define CDIM    256
#define HEADS   8
#define DH      32
#define KDIM    256
#define NQKV    768
#define MH      384
#define LOGIT_MAX 4.605170185988091f

// ---- scratch ----
__device__ float g_q[BW*HEADS*LW*DH];
__device__ float g_k[BW*HEADS*LW*DH];
__device__ float g_v[BW*HEADS*LW*DH];
__device__ float g_ao[BW*LW*CDIM];
__device__ float g_bias[HEADS*LW*LW];

// ============================================================
// helpers
// ============================================================
__device__ __forceinline__ float fast_exp(float x) {
    x = fmaxf(x, -87.0f);
    float y = x * 1.4426950408889634f;
    float n = rintf(y);
    float f = y - n;
    float p = 1.3333558146e-3f;
    p = fmaf(p, f, 9.6181291076e-3f);
    p = fmaf(p, f, 5.5504108664e-2f);
    p = fmaf(p, f, 2.4022650696e-1f);
    p = fmaf(p, f, 6.9314718056e-1f);
    p = fmaf(p, f, 1.0f);
    return p * __int_as_float(((int)n + 127) << 23);
}
__device__ __forceinline__ u32 smem_u32(const void* p) {
    u32 a;
    asm("{ .reg .u64 t; cvta.to.shared.u64 t, %1; cvt.u32.u64 %0, t; }" : "=r"(a) : "l"(p));
    return a;
}
// pack two f32 -> bf16x2; result<15:0> = lo arg, <31:16> = hi arg
__device__ __forceinline__ u32 bf16x2_rn(float lo, float hi) {
    u32 r; asm("cvt.rn.bf16x2.f32 %0, %1, %2;" : "=r"(r) : "f"(hi), "f"(lo)); return r;
}
__device__ __forceinline__ void ldsm4(u32* r, u32 addr) {
    asm volatile("ldmatrix.sync.aligned.m8n8.x4.shared.b16 {%0,%1,%2,%3}, [%4];"
        : "=r"(r[0]), "=r"(r[1]), "=r"(r[2]), "=r"(r[3]) : "r"(addr));
}
__device__ __forceinline__ void mma_bf16(float* d, const u32* a, u32 b0, u32 b1) {
    asm volatile("mma.sync.aligned.m16n8k16.row.col.f32.bf16.bf16.f32 "
        "{%0,%1,%2,%3}, {%4,%5,%6,%7}, {%8,%9}, {%0,%1,%2,%3};"
        : "+f"(d[0]), "+f"(d[1]), "+f"(d[2]), "+f"(d[3])
        : "r"(a[0]), "r"(a[1]), "r"(a[2]), "r"(a[3]), "r"(b0), "r"(b1));
}

// ============================================================
// 1) bias table (meta MLP)
// ============================================================
__global__ void bias_kernel(const float* __restrict__ fc1_w, const float* __restrict__ fc1_b,
                            const float* __restrict__ fc2_w, const float* __restrict__ fc2_b) {
    int idx = blockIdx.x * blockDim.x + threadIdx.x;
    if (idx >= LW*LW) return;
    int i = idx / LW, j = idx % LW;
    float dy = (float)(i / 12 - j / 12);
    float dx = (float)(i % 12 - j % 12);
    float ry = copysignf(log1pf(fabsf(dy)), dy);
    float rx = copysignf(log1pf(fabsf(dx)), dx);

    float out[HEADS];
    #pragma unroll
    for (int hh = 0; hh < HEADS; hh++) out[hh] = 0.0f;
    for (int t = 0; t < MH; t++) {
        float hsum = fmaf(fc1_w[t*2], ry, fmaf(fc1_w[t*2+1], rx, fc1_b[t]));
        hsum = fmaxf(hsum, 0.0f);
        #pragma unroll
        for (int hh = 0; hh < HEADS; hh++)
            out[hh] = fmaf(fc2_w[hh*MH + t], hsum, out[hh]);
    }
    #pragma unroll
    for (int hh = 0; hh < HEADS; hh++)
        g_bias[hh*LW*LW + idx] = out[hh] + fc2_b[hh];
}

// ============================================================
// mma.sync bf16x3 GEMM (unchanged from R5 — verified)
// ============================================================
#define APITCH 80

__device__ __forceinline__ void stage_tile(const float* __restrict__ A,
                                           const float* __restrict__ B,
                                           int m0, int n0, int kt,
                                           char* sAhi, char* sAlo, char* sBf) {
    int tid = threadIdx.x;
    #pragma unroll
    for (int j = 0; j < 8; j++) {
        int i = tid + j * 256;
        int ii = i & 1023;
        int row = ii >> 3, c4 = ii & 7;
        const float* src = (i < 1024)
            ? (A + (long)(m0 + row) * KDIM + kt * 32 + c4 * 4)
            : (B + (long)(n0 + row) * KDIM + kt * 32 + c4 * 4);
        float4 v = *(const float4*)src;
        u32 h01 = bf16x2_rn(v.x, v.y);
        u32 h23 = bf16x2_rn(v.z, v.w);
        float hx = __uint_as_float(h01 << 16);
        float hy = __uint_as_float(h01 & 0xFFFF0000u);
        float hz = __uint_as_float(h23 << 16);
        float hw = __uint_as_float(h23 & 0xFFFF0000u);
        u32 l01 = bf16x2_rn(v.x - hx, v.y - hy);
        u32 l23 = bf16x2_rn(v.z - hz, v.w - hw);
        if (i < 1024) {
            int off = row * APITCH + c4 * 8;
            *(uint2*)(sAhi + off) = make_uint2(h01, h23);
            *(uint2*)(sAlo + off) = make_uint2(l01, l23);
        } else {
            int s = c4 >> 2;
            int khalf = (c4 >> 1) & 1;
            int l = ((row & 7) << 2) + ((c4 & 1) << 1);
            int nt = row >> 3;
            int base = ((s * 16 + nt) * 32 + l) << 4;
            *(u32*)(sBf + base + khalf * 4)       = h01;
            *(u32*)(sBf + base + 8 + khalf * 4)   = l01;
            *(u32*)(sBf + base + 16 + khalf * 4)  = h23;
            *(u32*)(sBf + base + 24 + khalf * 4)  = l23;
        }
    }
}

struct GemmSmem {
    __align__(16) char sAhi[128 * APITCH];
    __align__(16) char sAlo[128 * APITCH];
    __align__(16) char sBf[2 * 16 * 32 * 16];
};

__device__ __forceinline__ void gemm_mma(const float* __restrict__ A,
                                         const float* __restrict__ B,
                                         int m0, int n0,
                                         GemmSmem* sm, float acc[2][8][4]) {
    int tid = threadIdx.x, lane = tid & 31, wid = tid >> 5;
    int wm = wid >> 1, wn = wid & 1;

    #pragma unroll
    for (int mt = 0; mt < 2; mt++)
        #pragma unroll
        for (int nt = 0; nt < 8; nt++)
            #pragma unroll
            for (int c = 0; c < 4; c++) acc[mt][nt][c] = 0.0f;

    u32 aAhi = smem_u32(sm->sAhi), aAlo = smem_u32(sm->sAlo);
    u32 rowA = (u32)((wm * 32 + (lane & 15)) * APITCH + ((lane >> 4) << 4));

    for (int kt = 0; kt < 8; kt++) {
        stage_tile(A, B, m0, n0, kt, sm->sAhi, sm->sAlo, sm->sBf);
        __syncthreads();
        #pragma unroll
        for (int s = 0; s < 2; s++) {
            u32 ah[2][4], al[2][4];
            #pragma unroll
            for (int mt = 0; mt < 2; mt++) {
                u32 ad = rowA + mt * 16 * APITCH + s * 32;
                ldsm4(ah[mt], aAhi + ad);
                ldsm4(al[mt], aAlo + ad);
            }
            #pragma unroll
            for (int nt2 = 0; nt2 < 8; nt2++) {
                uint4 b = *(const uint4*)(sm->sBf +
                    (((s * 16 + wn * 8 + nt2) * 32 + lane) << 4));
                #pragma unroll
                for (int mt = 0; mt < 2; mt++) {
                    mma_bf16(acc[mt][nt2], ah[mt], b.x, b.y);
                    mma_bf16(acc[mt][nt2], al[mt], b.x, b.y);
                    mma_bf16(acc[mt][nt2], ah[mt], b.z, b.w);
                }
            }
        }
        __syncthreads();
    }
}

// ============================================================
// 2) QKV GEMM kernel
// ============================================================
__global__ void __launch_bounds__(256, 2)
qkv_mma_kernel(const float* __restrict__ X, const float* __restrict__ W,
               const float* __restrict__ bias) {
    __shared__ GemmSmem sm;
    int m0 = blockIdx.y * 128;
    int n0 = blockIdx.x * 128;
    float acc[2][8][4];
    gemm_mma(X, W, m0, n0, &sm, acc);

    int lane = threadIdx.x & 31, wid = threadIdx.x >> 5;
    int wm = wid >> 1, wn = wid & 1;
    int r = lane >> 2, cp = (lane & 3) * 2;

    #pragma unroll
    for (int mt = 0; mt < 2; mt++) {
        #pragma unroll
        for (int half = 0; half < 2; half++) {
            int m = m0 + wm * 32 + mt * 16 + r + half * 8;
            int b = m / LW, l = m % LW;
            #pragma unroll
            for (int nt2 = 0; nt2 < 8; nt2++) {
                int col = n0 + wn * 64 + nt2 * 8 + cp;
                int part = col >> 8;
                int h = (col >> 5) & 7;
                int d0 = col & 31;
                float* dst = (part == 0) ? g_q : ((part == 1) ? g_k : g_v);
                float2 v;
                v.x = acc[mt][nt2][half * 2 + 0] + bias[col];
                v.y = acc[mt][nt2][half * 2 + 1] + bias[col + 1];
                *(float2*)(dst + ((long)(b * HEADS + h) * LW + l) * DH + d0) = v;
            }
        }
    }
}

// ============================================================
// 3) Attention: flash-style mma.sync bf16x3
//    block = (b,h), 160 threads = 5 warps, warp = 2 m16 tiles (last: 1)
// ============================================================
#define QPITCH 80     // bytes per Q row (64 data + 16 pad) -> conflict-free ldsm
#define VPITCH 304    // bytes per Vt row (288 data + 16 pad) -> conflict-free u32
#define OQH 0
#define OQL 11520
#define OKF 23040                 // 2*18*32*16 = 18432
#define OVH 41472                 // 32*304 = 9728
#define OVL 51200
#define ATTN_SMEM 60928

__global__ void __launch_bounds__(160)
attn_mma_kernel(const float* __restrict__ mask,
                const float* __restrict__ logit_scale, int num_win) {
    extern __shared__ char sm[];
    char* sQh = sm + OQH;
    char* sQl = sm + OQL;
    char* sKf = sm + OKF;
    char* sVh = sm + OVH;
    char* sVl = sm + OVL;

    int h = blockIdx.x & 7;
    int b = blockIdx.x >> 3;
    int tid = threadIdx.x;
    long base = (long)(b * HEADS + h) * LW * DH;
    float scale = fast_exp(fminf(logit_scale[h], LOGIT_MAX));

    // ---- staging: thread r handles row r of Q, K, V ----
    if (tid < LW) {
        int r = tid;
        // K: normalize row, bf16 hi/lo split, fragment-order scatter (NT=18)
        {
            const float4* kp = (const float4*)(g_k + base + (long)r * DH);
            float4 kr[8]; float ss = 0.0f;
            #pragma unroll
            for (int i = 0; i < 8; i++) {
                kr[i] = kp[i];
                ss = fmaf(kr[i].x, kr[i].x, ss); ss = fmaf(kr[i].y, kr[i].y, ss);
                ss = fmaf(kr[i].z, kr[i].z, ss); ss = fmaf(kr[i].w, kr[i].w, ss);
            }
            float inv = 1.0f / fmaxf(sqrtf(ss), 1e-12f);
            #pragma unroll
            for (int c4 = 0; c4 < 8; c4++) {
                float vx = kr[c4].x * inv, vy = kr[c4].y * inv;
                float vz = kr[c4].z * inv, vw = kr[c4].w * inv;
                u32 h01 = bf16x2_rn(vx, vy), h23 = bf16x2_rn(vz, vw);
                u32 l01 = bf16x2_rn(vx - __uint_as_float(h01 << 16),
                                    vy - __uint_as_float(h01 & 0xFFFF0000u));
                u32 l23 = bf16x2_rn(vz - __uint_as_float(h23 << 16),
                                    vw - __uint_as_float(h23 & 0xFFFF0000u));
                int s = c4 >> 2, khalf = (c4 >> 1) & 1;
                int l = ((r & 7) << 2) + ((c4 & 1) << 1);
                int nt = r >> 3;
                char* p = sKf + (((s * 18 + nt) * 32 + l) << 4);
                *(u32*)(p + khalf * 4)      = h01;
                *(u32*)(p + 8 + khalf * 4)  = l01;
                *(u32*)(p + 16 + khalf * 4) = h23;
                *(u32*)(p + 24 + khalf * 4) = l23;
            }
        }
        // Q: normalize+scale, row-major store
        {
            const float4* qp = (const float4*)(g_q + base + (long)r * DH);
            float4 qr[8]; float ss = 0.0f;
            #pragma unroll
            for (int i = 0; i < 8; i++) {
                qr[i] = qp[i];
                ss = fmaf(qr[i].x, qr[i].x, ss); ss = fmaf(qr[i].y, qr[i].y, ss);
                ss = fmaf(qr[i].z, qr[i].z, ss); ss = fmaf(qr[i].w, qr[i].w, ss);
            }
            float inv = scale / fmaxf(sqrtf(ss), 1e-12f);
            #pragma unroll
            for (int c4 = 0; c4 < 8; c4++) {
                float vx = qr[c4].x * inv, vy = qr[c4].y * inv;
                float vz = qr[c4].z * inv, vw = qr[c4].w * inv;
                u32 h01 = bf16x2_rn(vx, vy), h23 = bf16x2_rn(vz, vw);
                u32 l01 = bf16x2_rn(vx - __uint_as_float(h01 << 16),
                                    vy - __uint_as_float(h01 & 0xFFFF0000u));
                u32 l23 = bf16x2_rn(vz - __uint_as_float(h23 << 16),
                                    vw - __uint_as_float(h23 & 0xFFFF0000u));
                *(uint2*)(sQh + r * QPITCH + c4 * 8) = make_uint2(h01, h23);
                *(uint2*)(sQl + r * QPITCH + c4 * 8) = make_uint2(l01, l23);
            }
        }
        // V: transpose to [dim][key], bf16 hi/lo
        {
            const float4* vp = (const float4*)(g_v + base + (long)r * DH);
            #pragma unroll
            for (int c4 = 0; c4 < 8; c4++) {
                float4 v = vp[c4];
                u32 h01 = bf16x2_rn(v.x, v.y), h23 = bf16x2_rn(v.z, v.w);
                u32 l01 = bf16x2_rn(v.x - __uint_as_float(h01 << 16),
                                    v.y - __uint_as_float(h01 & 0xFFFF0000u));
                u32 l23 = bf16x2_rn(v.z - __uint_as_float(h23 << 16),
                                    v.w - __uint_as_float(h23 & 0xFFFF0000u));
                int d = c4 * 4;
                *(unsigned short*)(sVh + (d+0)*VPITCH + r*2) = (unsigned short)(h01 & 0xFFFFu);
                *(unsigned short*)(sVh + (d+1)*VPITCH + r*2) = (unsigned short)(h01 >> 16);
                *(unsigned short*)(sVh + (d+2)*VPITCH + r*2) = (unsigned short)(h23 & 0xFFFFu);
                *(unsigned short*)(sVh + (d+3)*VPITCH + r*2) = (unsigned short)(h23 >> 16);
                *(unsigned short*)(sVl + (d+0)*VPITCH + r*2) = (unsigned short)(l01 & 0xFFFFu);
                *(unsigned short*)(sVl + (d+1)*VPITCH + r*2) = (unsigned short)(l01 >> 16);
                *(unsigned short*)(sVl + (d+2)*VPITCH + r*2) = (unsigned short)(l23 & 0xFFFFu);
                *(unsigned short*)(sVl + (d+3)*VPITCH + r*2) = (unsigned short)(l23 >> 16);
            }
        }
    }
    __syncthreads();

    int lane = tid & 31, w = tid >> 5;
    int r4 = lane >> 2, c4l = lane & 3;
    int mstart = 2 * w;
    int mcount = (w == 4) ? 1 : 2;
    int wi = b % num_win;
    u32 aQh = smem_u32(sQh), aQl = smem_u32(sQl);

    for (int mi = 0; mi < mcount; mi++) {
        int mt = mstart + mi;
        int row0 = mt * 16 + r4;

        // A fragments for Q (2 k16 steps, hi+lo)
        u32 qh[2][4], ql[2][4];
        u32 arow = (u32)((mt * 16 + (lane & 15)) * QPITCH + ((lane >> 4) << 4));
        ldsm4(qh[0], aQh + arow);
        ldsm4(qh[1], aQh + arow + 32);
        ldsm4(ql[0], aQl + arow);
        ldsm4(ql[1], aQl + arow + 32);

        // S = Qn * Kn^T  (full 144-col row block in regs)
        float sfr[18][4];
        #pragma unroll
        for (int j = 0; j < 18; j++)
            #pragma unroll
            for (int q = 0; q < 4; q++) sfr[j][q] = 0.0f;

        #pragma unroll
        for (int j = 0; j < 18; j++) {
            #pragma unroll
            for (int s = 0; s < 2; s++) {
                uint4 bb = *(const uint4*)(sKf + (((s * 18 + j) * 32 + lane) << 4));
                mma_bf16(sfr[j], qh[s], bb.x, bb.y);
                mma_bf16(sfr[j], ql[s], bb.x, bb.y);
                mma_bf16(sfr[j], qh[s], bb.z, bb.w);
            }
        }

        // bias + mask + row max
        const float* br0 = g_bias + ((long)h * LW + row0) * LW;
        const float* br1 = br0 + 8 * LW;
        const float* mr0 = mask + ((long)wi * LW + row0) * LW;
        const float* mr1 = mr0 + 8 * LW;
        float mx0 = -1e30f, mx1 = -1e30f;
        #pragma unroll
        for (int j = 0; j < 18; j++) {
            int col = j * 8 + c4l * 2;
            float2 b0 = *(const float2*)(br0 + col);
            float2 m0 = *(const float2*)(mr0 + col);
            float2 b1 = *(const float2*)(br1 + col);
            float2 m1 = *(const float2*)(mr1 + col);
            sfr[j][0] += b0.x + m0.x; sfr[j][1] += b0.y + m0.y;
            sfr[j][2] += b1.x + m1.x; sfr[j][3] += b1.y + m1.y;
            mx0 = fmaxf(mx0, fmaxf(sfr[j][0], sfr[j][1]));
            mx1 = fmaxf(mx1, fmaxf(sfr[j][2], sfr[j][3]));
        }
        mx0 = fmaxf(mx0, __shfl_xor_sync(0xFFFFFFFFu, mx0, 1));
        mx0 = fmaxf(mx0, __shfl_xor_sync(0xFFFFFFFFu, mx0, 2));
        mx1 = fmaxf(mx1, __shfl_xor_sync(0xFFFFFFFFu, mx1, 1));
        mx1 = fmaxf(mx1, __shfl_xor_sync(0xFFFFFFFFu, mx1, 2));

        // exp + partial sums
        float sum0 = 0.0f, sum1 = 0.0f;
        #pragma unroll
        for (int j = 0; j < 18; j++) {
            float p0 = fast_exp(sfr[j][0] - mx0);
            float p1 = fast_exp(sfr[j][1] - mx0);
            float p2 = fast_exp(sfr[j][2] - mx1);
            float p3 = fast_exp(sfr[j][3] - mx1);
            sfr[j][0] = p0; sfr[j][1] = p1; sfr[j][2] = p2; sfr[j][3] = p3;
            sum0 += p0 + p1; sum1 += p2 + p3;
        }
        sum0 += __shfl_xor_sync(0xFFFFFFFFu, sum0, 1);
        sum0 += __shfl_xor_sync(0xFFFFFFFFu, sum0, 2);
        sum1 += __shfl_xor_sync(0xFFFFFFFFu, sum1, 1);
        sum1 += __shfl_xor_sync(0xFFFFFFFFu, sum1, 2);

        // O = P * V  (P fragments come straight from S C-fragments)
        float o[4][4];
        #pragma unroll
        for (int n = 0; n < 4; n++)
            #pragma unroll
            for (int q = 0; q < 4; q++) o[n][q] = 0.0f;

        #pragma unroll
        for (int t = 0; t < 9; t++) {
            u32 ph[4], pl[4];
            ph[0] = bf16x2_rn(sfr[2*t][0], sfr[2*t][1]);
            ph[1] = bf16x2_rn(sfr[2*t][2], sfr[2*t][3]);
            ph[2] = bf16x2_rn(sfr[2*t+1][0], sfr[2*t+1][1]);
            ph[3] = bf16x2_rn(sfr[2*t+1][2], sfr[2*t+1][3]);
            pl[0] = bf16x2_rn(sfr[2*t][0]   - __uint_as_float(ph[0] << 16),
                              sfr[2*t][1]   - __uint_as_float(ph[0] & 0xFFFF0000u));
            pl[1] = bf16x2_rn(sfr[2*t][2]   - __uint_as_float(ph[1] << 16),
                              sfr[2*t][3]   - __uint_as_float(ph[1] & 0xFFFF0000u));
            pl[2] = bf16x2_rn(sfr[2*t+1][0] - __uint_as_float(ph[2] << 16),
                              sfr[2*t+1][1] - __uint_as_float(ph[2] & 0xFFFF0000u));
            pl[3] = bf16x2_rn(sfr[2*t+1][2] - __uint_as_float(ph[3] << 16),
                              sfr[2*t+1][3] - __uint_as_float(ph[3] & 0xFFFF0000u));
            int kb = t * 32 + c4l * 4;   // byte offset: key 16t+2c
            #pragma unroll
            for (int n = 0; n < 4; n++) {
                int vrow = (n * 8 + r4) * VPITCH;
                u32 b0h = *(const u32*)(sVh + vrow + kb);
                u32 b1h = *(const u32*)(sVh + vrow + kb + 16);
                u32 b0l = *(const u32*)(sVl + vrow + kb);
                u32 b1l = *(const u32*)(sVl + vrow + kb + 16);
                mma_bf16(o[n], ph, b0h, b1h);
                mma_bf16(o[n], pl, b0h, b1h);
                mma_bf16(o[n], ph, b0l, b1l);
            }
        }

        float i0 = 1.0f / sum0, i1 = 1.0f / sum1;
        float* op0 = g_ao + ((long)b * LW + row0) * CDIM + h * DH + c4l * 2;
        float* op1 = op0 + 8 * CDIM;
        #pragma unroll
        for (int n = 0; n < 4; n++) {
            *(float2*)(op0 + n * 8) = make_float2(o[n][0] * i0, o[n][1] * i0);
            *(float2*)(op1 + n * 8) = make_float2(o[n][2] * i1, o[n][3] * i1);
        }
    }
}

// ============================================================
// 4) Output projection
// ============================================================
__global__ void __launch_bounds__(256, 2)
proj_mma_kernel(const float* __restrict__ W, const float* __restrict__ bias,
                float* __restrict__ out) {
    __shared__ GemmSmem sm;
    int m0 = blockIdx.y * 128;
    int n0 = blockIdx.x * 128;
    float acc[2][8][4];
    gemm_mma(g_ao, W, m0, n0, &sm, acc);

    int lane = threadIdx.x & 31, wid = threadIdx.x >> 5;
    int wm = wid >> 1, wn = wid & 1;
    int r = lane >> 2, cp = (lane & 3) * 2;

    #pragma unroll
    for (int mt = 0; mt < 2; mt++) {
        #pragma unroll
        for (int half = 0; half < 2; half++) {
            int m = m0 + wm * 32 + mt * 16 + r + half * 8;
            #pragma unroll
            for (int nt2 = 0; nt2 < 8; nt2++) {
                int col = n0 + wn * 64 + nt2 * 8 + cp;
                float2 v;
                v.x = acc[mt][nt2][half * 2 + 0] + bias[col];
                v.y = acc[mt][nt2][half * 2 + 1] + bias[col + 1];
                *(float2*)(out + (long)m * CDIM + col) = v;
            }
        }
    }
}

// ============================================================
// launch
// ============================================================
extern "C" void kernel_launch(void* const* d_in, const int* in_sizes, int n_in,
                              void* d_out, int out_size) {
    const float* x           = (const float*)d_in[0];
    const float* mask        = (const float*)d_in[1];
    const float* qkv_w       = (const float*)d_in[2];
    const float* qkv_b       = (const float*)d_in[3];
    const float* proj_w      = (const float*)d_in[4];
    const float* proj_b      = (const float*)d_in[5];
    const float* fc1_w       = (const float*)d_in[6];
    const float* fc1_b       = (const float*)d_in[7];
    const float* fc2_w       = (const float*)d_in[8];
    const float* fc2_b       = (const float*)d_in[9];
    const float* logit_scale = (const float*)d_in[10];

    int Bw = in_sizes[0] / (LW * CDIM);       // 1024
    int num_win = in_sizes[1] / (LW * LW);    // 64
    int Mrows = Bw * LW;                      // 147456

    static int smem_set = 0;
    if (!smem_set) {
        cudaFuncSetAttribute(attn_mma_kernel,
                             cudaFuncAttributeMaxDynamicSharedMemorySize, ATTN_SMEM);
        smem_set = 1;
    }

    bias_kernel<<<(LW*LW + 63) / 64, 64>>>(fc1_w, fc1_b, fc2_w, fc2_b);
    qkv_mma_kernel<<<dim3(NQKV / 128, Mrows / 128), 256>>>(x, qkv_w, qkv_b);
    attn_mma_kernel<<<Bw * HEADS, 160, ATTN_SMEM>>>(mask, logit_scale, num_win);
    proj_mma_kernel<<<dim3(CDIM / 128, Mrows / 128), 256>>>(proj_w, proj_b, (float*)d_out);
}